// round 4
// baseline (speedup 1.0000x reference)
#include <cuda_runtime.h>
#include <cstdint>

#define N_NODES 100000
#define HID     64

// Scratch (no allocations allowed) — 3 x 25.6 MB
__device__ float g_h0[(size_t)N_NODES * HID];
__device__ float g_h1[(size_t)N_NODES * HID];
__device__ float g_agg[(size_t)N_NODES * HID];

// ---------------------------------------------------------------------------
// Register-tiled GEMM: C[n_rows, ncols] = act( (A (+A2)) @ B + bias )
// A row-major [n_rows, KDIM], B row-major [KDIM, ldb] (first ncols used),
// C row-major ldc. Block: 64 rows x 64 cols, 256 threads, 4x4 per thread.
// ---------------------------------------------------------------------------
template<int KDIM, bool ADD_AGG, bool RELU>
__global__ void __launch_bounds__(256)
gemm_kernel(const float* __restrict__ A, const float* __restrict__ A2,
            const float* __restrict__ B, const float* __restrict__ bias,
            float* __restrict__ C, int n_rows, int ncols, int ldb, int ldc)
{
    __shared__ float As[64][36];        // 32-wide K tile, padded
    __shared__ float Bs[KDIM][64];      // full B panel
    __shared__ float bsh[64];

    const int tx = threadIdx.x & 15;    // col group 0..15  -> cols 4*tx..4*tx+3
    const int ty = threadIdx.x >> 4;    // row group 0..15  -> rows 4*ty..4*ty+3
    const int row0 = blockIdx.x * 64;

    // One-time load of B panel (+zero pad for ncols<64) and bias
    for (int i = threadIdx.x; i < KDIM * 64; i += 256) {
        int k = i >> 6, c = i & 63;
        Bs[k][c] = (c < ncols) ? B[k * ldb + c] : 0.f;
    }
    if (threadIdx.x < 64)
        bsh[threadIdx.x] = (threadIdx.x < ncols) ? bias[threadIdx.x] : 0.f;

    float acc[4][4];
#pragma unroll
    for (int i = 0; i < 4; i++)
#pragma unroll
        for (int j = 0; j < 4; j++) acc[i][j] = 0.f;

#pragma unroll 1
    for (int kk = 0; kk < KDIM; kk += 32) {
        __syncthreads();
        // Load A tile: 64 rows x 32 cols = 512 float4, 2 per thread (coalesced)
#pragma unroll
        for (int l = 0; l < 2; l++) {
            int idx = threadIdx.x + l * 256;
            int r   = idx >> 3;            // 0..63
            int k4  = (idx & 7) << 2;      // 0,4,...,28
            int row = row0 + r;
            float4 v = make_float4(0.f, 0.f, 0.f, 0.f);
            if (row < n_rows) {
                v = *(const float4*)(A + (size_t)row * KDIM + kk + k4);
                if (ADD_AGG) {
                    float4 w = *(const float4*)(A2 + (size_t)row * KDIM + kk + k4);
                    v.x += w.x; v.y += w.y; v.z += w.z; v.w += w.w;
                }
            }
            *(float4*)&As[r][k4] = v;
        }
        __syncthreads();

#pragma unroll 8
        for (int k = 0; k < 32; k++) {
            float4 b = *(const float4*)&Bs[kk + k][tx << 2];
            float a0 = As[(ty << 2) + 0][k];
            float a1 = As[(ty << 2) + 1][k];
            float a2 = As[(ty << 2) + 2][k];
            float a3 = As[(ty << 2) + 3][k];
            acc[0][0] += a0 * b.x; acc[0][1] += a0 * b.y; acc[0][2] += a0 * b.z; acc[0][3] += a0 * b.w;
            acc[1][0] += a1 * b.x; acc[1][1] += a1 * b.y; acc[1][2] += a1 * b.z; acc[1][3] += a1 * b.w;
            acc[2][0] += a2 * b.x; acc[2][1] += a2 * b.y; acc[2][2] += a2 * b.z; acc[2][3] += a2 * b.w;
            acc[3][0] += a3 * b.x; acc[3][1] += a3 * b.y; acc[3][2] += a3 * b.z; acc[3][3] += a3 * b.w;
        }
    }

    // Epilogue: bias (+ReLU), guarded store
#pragma unroll
    for (int i = 0; i < 4; i++) {
        int row = row0 + (ty << 2) + i;
        if (row >= n_rows) continue;
#pragma unroll
        for (int j = 0; j < 4; j++) {
            int col = (tx << 2) + j;
            if (col < ncols) {
                float v = acc[i][j] + bsh[col];
                if (RELU) v = fmaxf(v, 0.f);
                C[(size_t)row * ldc + col] = v;
            }
        }
    }
}

// ---------------------------------------------------------------------------
// Edge scatter: agg[dst[e]] += h[src[e]]  (64 floats per edge)
// 16 threads per edge, one float4 per thread, vector red (no return).
// ---------------------------------------------------------------------------
__global__ void __launch_bounds__(256)
scatter_kernel(const int* __restrict__ src, const int* __restrict__ dst,
               const float* __restrict__ h, float* __restrict__ agg, int E)
{
    int t = blockIdx.x * blockDim.x + threadIdx.x;
    int e = t >> 4;
    if (e >= E) return;
    int lane4 = (t & 15) << 2;  // 0,4,...,60

    int s = __ldg(src + e);
    int d = __ldg(dst + e);

    float4 v = *(const float4*)(h + (size_t)s * HID + lane4);
    float* p = agg + (size_t)d * HID + lane4;
    asm volatile("red.global.add.v4.f32 [%0], {%1, %2, %3, %4};"
                 :: "l"(p), "f"(v.x), "f"(v.y), "f"(v.z), "f"(v.w)
                 : "memory");
}

// ---------------------------------------------------------------------------
// Inputs (metadata order): x[N,128], edge_index[2,E], W_in[128,64], b_in[64],
// W_layers[3,64,64], b_layers[3,64], W_cls[64,40], b_cls[40].
// Output: float32 [N, 40].
// ---------------------------------------------------------------------------
extern "C" void kernel_launch(void* const* d_in, const int* in_sizes, int n_in,
                              void* d_out, int out_size)
{
    const float* x     = (const float*)d_in[0];
    const int*   ei    = (const int*)  d_in[1];
    const float* W_in  = (const float*)d_in[2];
    const float* b_in  = (const float*)d_in[3];
    const float* W_l   = (const float*)d_in[4];
    const float* b_l   = (const float*)d_in[5];
    const float* W_cls = (const float*)d_in[6];
    const float* b_cls = (const float*)d_in[7];

    const int n = in_sizes[0] / 128;
    const int E = in_sizes[1] / 2;
    const int* src = ei;
    const int* dst = ei + E;

    float *h0, *h1, *agg;
    cudaGetSymbolAddress((void**)&h0,  g_h0);
    cudaGetSymbolAddress((void**)&h1,  g_h1);
    cudaGetSymbolAddress((void**)&agg, g_agg);

    const int nblk = (n + 63) / 64;

    // h = relu(x @ W_in + b_in)
    gemm_kernel<128, false, true><<<nblk, 256>>>(x, nullptr, W_in, b_in, h0,
                                                 n, 64, 64, 64);

    float* hc = h0;
    float* hn = h1;
    const int sblk = (int)(((long long)E * 16 + 255) / 256);
    for (int i = 0; i < 3; i++) {
        cudaMemsetAsync(agg, 0, (size_t)n * HID * sizeof(float));
        scatter_kernel<<<sblk, 256>>>(src, dst, hc, agg, E);
        // h = relu((h + agg) @ W_layers[i] + b_layers[i])
        gemm_kernel<64, true, true><<<nblk, 256>>>(hc, agg,
                                                   W_l + (size_t)i * 64 * 64,
                                                   b_l + (size_t)i * 64,
                                                   hn, n, 64, 64, 64);
        float* tmp = hc; hc = hn; hn = tmp;
    }

    // out = h @ W_cls + b_cls   (40 cols)
    gemm_kernel<64, false, false><<<nblk, 256>>>(hc, nullptr, W_cls, b_cls,
                                                 (float*)d_out, n, 40, 40, 40);
}

// round 5
// speedup vs baseline: 1.3223x; 1.3223x over previous
#include <cuda_runtime.h>
#include <cstdint>

#define N_NODES 100000
#define MAX_E   2000000
#define HID     64
#define SCAN_B  1024

// Scratch (no allocations allowed)
__device__ float g_h0[(size_t)N_NODES * HID];
__device__ float g_h1[(size_t)N_NODES * HID];
__device__ float g_agg[(size_t)N_NODES * HID];
__device__ int   g_off[N_NODES + 1];      // row begin (exclusive scan of deg)
__device__ int   g_cursor[N_NODES];       // after fill: row end
__device__ int   g_bsum[(N_NODES + SCAN_B - 1) / SCAN_B + 1];
__device__ int   g_csr[MAX_E];

// ---------------------------------------------------------------------------
// CSR build: histogram of dst -> exclusive scan -> bucket fill
// ---------------------------------------------------------------------------
__global__ void hist_kernel(const int* __restrict__ dst, int* __restrict__ cnt, int E)
{
    int e = blockIdx.x * blockDim.x + threadIdx.x;
    if (e < E) atomicAdd(&cnt[dst[e]], 1);
}

__global__ void scan1_kernel(const int* __restrict__ deg, int* __restrict__ off,
                             int* __restrict__ bsum, int n)
{
    __shared__ int sh[SCAN_B];
    int i = blockIdx.x * SCAN_B + threadIdx.x;
    int v = (i < n) ? deg[i] : 0;
    sh[threadIdx.x] = v;
    __syncthreads();
#pragma unroll
    for (int d = 1; d < SCAN_B; d <<= 1) {
        int t = (threadIdx.x >= d) ? sh[threadIdx.x - d] : 0;
        __syncthreads();
        sh[threadIdx.x] += t;
        __syncthreads();
    }
    if (i < n) off[i] = sh[threadIdx.x] - v;   // exclusive
    if (threadIdx.x == SCAN_B - 1) bsum[blockIdx.x] = sh[threadIdx.x];
}

__global__ void scan2_kernel(int* __restrict__ bsum, int nb)
{
    if (threadIdx.x == 0) {
        int acc = 0;
        for (int i = 0; i < nb; i++) { int t = bsum[i]; bsum[i] = acc; acc += t; }
    }
}

__global__ void scan3_kernel(int* __restrict__ off, const int* __restrict__ bsum, int n)
{
    int i = blockIdx.x * SCAN_B + threadIdx.x;
    if (i < n) off[i] += bsum[blockIdx.x];
}

__global__ void fill_csr_kernel(const int* __restrict__ src, const int* __restrict__ dst,
                                int* __restrict__ cursor, int* __restrict__ csr, int E)
{
    int e = blockIdx.x * blockDim.x + threadIdx.x;
    if (e >= E) return;
    int pos = atomicAdd(&cursor[dst[e]], 1);
    csr[pos] = src[e];
}

// ---------------------------------------------------------------------------
// Aggregation (gather-only): out[v] = h[v] + sum_{u in in(v)} h[u]
// Row v of csr spans [beg[v], end[v]).  16 threads/node, float4 per lane.
// ---------------------------------------------------------------------------
__global__ void __launch_bounds__(256)
aggregate_kernel(const int* __restrict__ beg_arr, const int* __restrict__ end_arr,
                 const int* __restrict__ csr,
                 const float* __restrict__ h, float* __restrict__ out, int n)
{
    int t = blockIdx.x * blockDim.x + threadIdx.x;
    int g = t >> 4;
    if (g >= n) return;
    int lane    = threadIdx.x & 15;
    int c4      = lane << 2;
    unsigned hm = 0xFFFFu << (threadIdx.x & 16);

    int beg = beg_arr[g];
    int end = end_arr[g];

    float4 acc = *(const float4*)(h + (size_t)g * HID + c4);  // residual fused

    for (int base = beg; base < end; base += 16) {
        int idx = (base + lane < end) ? csr[base + lane] : 0;
        int cnt = min(16, end - base);
        for (int j = 0; j < cnt; j++) {
            int s = __shfl_sync(hm, idx, j, 16);
            float4 v = *(const float4*)(h + (size_t)s * HID + c4);
            acc.x += v.x; acc.y += v.y; acc.z += v.z; acc.w += v.w;
        }
    }
    *(float4*)(out + (size_t)g * HID + c4) = acc;
}

// ---------------------------------------------------------------------------
// Register-tiled GEMM: C = act(A @ B + bias), 64x64 block, 4x4/thread.
// ---------------------------------------------------------------------------
template<int KDIM, bool RELU>
__global__ void __launch_bounds__(256)
gemm_kernel(const float* __restrict__ A,
            const float* __restrict__ B, const float* __restrict__ bias,
            float* __restrict__ C, int n_rows, int ncols, int ldb, int ldc)
{
    __shared__ float As[64][36];
    __shared__ float Bs[KDIM][64];
    __shared__ float bsh[64];

    const int tx = threadIdx.x & 15;
    const int ty = threadIdx.x >> 4;
    const int row0 = blockIdx.x * 64;

    for (int i = threadIdx.x; i < KDIM * 64; i += 256) {
        int k = i >> 6, c = i & 63;
        Bs[k][c] = (c < ncols) ? B[k * ldb + c] : 0.f;
    }
    if (threadIdx.x < 64)
        bsh[threadIdx.x] = (threadIdx.x < ncols) ? bias[threadIdx.x] : 0.f;

    float acc[4][4];
#pragma unroll
    for (int i = 0; i < 4; i++)
#pragma unroll
        for (int j = 0; j < 4; j++) acc[i][j] = 0.f;

#pragma unroll 1
    for (int kk = 0; kk < KDIM; kk += 32) {
        __syncthreads();
#pragma unroll
        for (int l = 0; l < 2; l++) {
            int idx = threadIdx.x + l * 256;
            int r   = idx >> 3;
            int k4  = (idx & 7) << 2;
            int row = row0 + r;
            float4 v = make_float4(0.f, 0.f, 0.f, 0.f);
            if (row < n_rows)
                v = *(const float4*)(A + (size_t)row * KDIM + kk + k4);
            *(float4*)&As[r][k4] = v;
        }
        __syncthreads();

#pragma unroll 8
        for (int k = 0; k < 32; k++) {
            float4 b = *(const float4*)&Bs[kk + k][tx << 2];
            float a0 = As[(ty << 2) + 0][k];
            float a1 = As[(ty << 2) + 1][k];
            float a2 = As[(ty << 2) + 2][k];
            float a3 = As[(ty << 2) + 3][k];
            acc[0][0] += a0 * b.x; acc[0][1] += a0 * b.y; acc[0][2] += a0 * b.z; acc[0][3] += a0 * b.w;
            acc[1][0] += a1 * b.x; acc[1][1] += a1 * b.y; acc[1][2] += a1 * b.z; acc[1][3] += a1 * b.w;
            acc[2][0] += a2 * b.x; acc[2][1] += a2 * b.y; acc[2][2] += a2 * b.z; acc[2][3] += a2 * b.w;
            acc[3][0] += a3 * b.x; acc[3][1] += a3 * b.y; acc[3][2] += a3 * b.z; acc[3][3] += a3 * b.w;
        }
    }

#pragma unroll
    for (int i = 0; i < 4; i++) {
        int row = row0 + (ty << 2) + i;
        if (row >= n_rows) continue;
#pragma unroll
        for (int j = 0; j < 4; j++) {
            int col = (tx << 2) + j;
            if (col < ncols) {
                float v = acc[i][j] + bsh[col];
                if (RELU) v = fmaxf(v, 0.f);
                C[(size_t)row * ldc + col] = v;
            }
        }
    }
}

// ---------------------------------------------------------------------------
extern "C" void kernel_launch(void* const* d_in, const int* in_sizes, int n_in,
                              void* d_out, int out_size)
{
    const float* x     = (const float*)d_in[0];
    const int*   ei    = (const int*)  d_in[1];
    const float* W_in  = (const float*)d_in[2];
    const float* b_in  = (const float*)d_in[3];
    const float* W_l   = (const float*)d_in[4];
    const float* b_l   = (const float*)d_in[5];
    const float* W_cls = (const float*)d_in[6];
    const float* b_cls = (const float*)d_in[7];

    const int n = in_sizes[0] / 128;
    const int E = in_sizes[1] / 2;
    const int* src = ei;
    const int* dst = ei + E;

    float *h0, *h1, *agg;
    int *off, *cursor, *bsum, *csr;
    cudaGetSymbolAddress((void**)&h0,     g_h0);
    cudaGetSymbolAddress((void**)&h1,     g_h1);
    cudaGetSymbolAddress((void**)&agg,    g_agg);
    cudaGetSymbolAddress((void**)&off,    g_off);
    cudaGetSymbolAddress((void**)&cursor, g_cursor);
    cudaGetSymbolAddress((void**)&bsum,   g_bsum);
    cudaGetSymbolAddress((void**)&csr,    g_csr);

    const int nblk  = (n + 63) / 64;
    const int nscan = (n + SCAN_B - 1) / SCAN_B;
    const int eblk  = (E + 255) / 256;

    // ---- CSR build (dst-grouped) ----
    cudaMemsetAsync(off, 0, (size_t)n * sizeof(int));
    hist_kernel<<<eblk, 256>>>(dst, off, E);                 // off = deg (temp)
    scan1_kernel<<<nscan, SCAN_B>>>(off, cursor, bsum, n);   // cursor = per-block excl scan
    scan2_kernel<<<1, 32>>>(bsum, nscan);
    scan3_kernel<<<nscan, SCAN_B>>>(cursor, bsum, n);        // cursor = global excl scan
    cudaMemcpyAsync(off, cursor, (size_t)n * sizeof(int),
                    cudaMemcpyDeviceToDevice);               // off = row begins (preserved)
    fill_csr_kernel<<<eblk, 256>>>(src, dst, cursor, csr, E);
    // post: cursor[v] == row end of v

    // ---- h = relu(x @ W_in + b_in) ----
    gemm_kernel<128, true><<<nblk, 256>>>(x, W_in, b_in, h0, n, 64, 64, 64);

    float* hc = h0;
    float* hn = h1;
    const int ablk = (n * 16 + 255) / 256;
    for (int i = 0; i < 3; i++) {
        aggregate_kernel<<<ablk, 256>>>(off, cursor, csr, hc, agg, n);
        gemm_kernel<64, true><<<nblk, 256>>>(agg,
                                             W_l + (size_t)i * 64 * 64,
                                             b_l + (size_t)i * 64,
                                             hn, n, 64, 64, 64);
        float* tmp = hc; hc = hn; hn = tmp;
    }

    gemm_kernel<64, false><<<nblk, 256>>>(hc, W_cls, b_cls,
                                          (float*)d_out, n, 40, 40, 40);
}